// round 16
// baseline (speedup 1.0000x reference)
#include <cuda_runtime.h>
#include <cuda_bf16.h>
#include <cstdint>

#define D    128
#define CAP  256
#define NTH  256

// smem layout (bytes)
#define OFF_RH   0          // 16KB: 64 R-rows (this CTA's N-half) x 256B swizzled
#define OFF_RL   16384      // 16KB
#define OFF_AH   32768      // 8KB: 32 A-rows x 256B
#define OFF_AL   40960      // 8KB
#define OFF_SIDX 49152      // 1KB
#define OFF_SROW 50176      // 32*4
#define OFF_PSC  50304      // 32*4*4 = 512B
#define SMEM_BYTES 50816

// ---------------- helpers ----------------
__device__ __forceinline__ uint32_t smem_u32(const void* p) {
    return (uint32_t)__cvta_generic_to_shared(p);
}
__device__ __forceinline__ int swz(int row, int kbyte) {
    return row * 256 + (kbyte ^ ((row & 7) << 4));
}
__device__ __forceinline__ uint32_t pkbf(__nv_bfloat16 a, __nv_bfloat16 b) {
    return (uint32_t)__bfloat16_as_ushort(a) | ((uint32_t)__bfloat16_as_ushort(b) << 16);
}
__device__ __forceinline__ void split4(float4 v, uint2& hi, uint2& lo) {
    __nv_bfloat16 hx = __float2bfloat16(v.x), hy = __float2bfloat16(v.y);
    __nv_bfloat16 hz = __float2bfloat16(v.z), hw = __float2bfloat16(v.w);
    __nv_bfloat16 lx = __float2bfloat16(v.x - __bfloat162float(hx));
    __nv_bfloat16 ly = __float2bfloat16(v.y - __bfloat162float(hy));
    __nv_bfloat16 lz = __float2bfloat16(v.z - __bfloat162float(hz));
    __nv_bfloat16 lw = __float2bfloat16(v.w - __bfloat162float(hw));
    hi.x = pkbf(hx, hy); hi.y = pkbf(hz, hw);
    lo.x = pkbf(lx, ly); lo.y = pkbf(lz, lw);
}
__device__ __forceinline__ void ldsm_x4(uint32_t& r0, uint32_t& r1,
                                        uint32_t& r2, uint32_t& r3, uint32_t a) {
    asm volatile("ldmatrix.sync.aligned.m8n8.x4.shared.b16 {%0,%1,%2,%3}, [%4];"
                 : "=r"(r0), "=r"(r1), "=r"(r2), "=r"(r3) : "r"(a));
}
__device__ __forceinline__ void mma_bf16(float& c0, float& c1, float& c2, float& c3,
                                         uint32_t a0, uint32_t a1, uint32_t a2,
                                         uint32_t a3, uint32_t b0, uint32_t b1) {
    asm volatile(
        "mma.sync.aligned.m16n8k16.row.col.f32.bf16.bf16.f32 "
        "{%0,%1,%2,%3}, {%4,%5,%6,%7}, {%8,%9}, {%0,%1,%2,%3};"
        : "+f"(c0), "+f"(c1), "+f"(c2), "+f"(c3)
        : "r"(a0), "r"(a1), "r"(a2), "r"(a3), "r"(b0), "r"(b1));
}

// ---------------- out pre-zero (atomicAdd combine target) ----------------
__global__ void k_zero_out(float* __restrict__ out, int nelem) {
    int i = blockIdx.x * blockDim.x + threadIdx.x;
    if (i < nelem) out[i] = 0.f;
}

// ---------------- main kernel: one CTA per (relation, side, N-half) ----------------
extern "C" __global__ void __launch_bounds__(NTH, 4)
k_rescal(const int*   __restrict__ heads,
         const int*   __restrict__ tails,
         const int*   __restrict__ nheads,
         const int*   __restrict__ ntails,
         const int*   __restrict__ rels,
         const float* __restrict__ ent,
         const float* __restrict__ relm,
         float*       __restrict__ out,
         int B)
{
    extern __shared__ char sm[];
    __shared__ int s_cnt;
    int*   sidx = (int*)(sm + OFF_SIDX);
    int*   srow = (int*)(sm + OFF_SROW);     // head-row ids of current tile
    float* psc  = (float*)(sm + OFF_PSC);    // [32 rows][4 quarters]

    const int tid   = threadIdx.x;
    const int wid   = tid >> 5;
    const int lane  = tid & 31;
    const int r     = blockIdx.x >> 2;
    const int side  = (blockIdx.x >> 1) & 1;
    const int nhalf = blockIdx.x & 1;
    const int* tarr = side ? ntails : tails;
    const int* harr = side ? nheads : heads;

    if (tid == 0) s_cnt = 0;
    __syncthreads();

    // ---- PHASE 1 (parallel): warps 0-4 filter, warps 5-7 stage R half ----
    if (tid < 160) {
        const int4* r4 = (const int4*)rels;
        const int nq = B >> 2;
        for (int q = tid; q < nq; q += 160) {
            int4 v = r4[q];
            int base = q << 2;
            if (v.x == r) { int p = atomicAdd(&s_cnt, 1); if (p < CAP) sidx[p] = base; }
            if (v.y == r) { int p = atomicAdd(&s_cnt, 1); if (p < CAP) sidx[p] = base + 1; }
            if (v.z == r) { int p = atomicAdd(&s_cnt, 1); if (p < CAP) sidx[p] = base + 2; }
            if (v.w == r) { int p = atomicAdd(&s_cnt, 1); if (p < CAP) sidx[p] = base + 3; }
        }
        for (int i = (nq << 2) + tid; i < B; i += 160)
            if (rels[i] == r) { int p = atomicAdd(&s_cnt, 1); if (p < CAP) sidx[p] = i; }
    } else {
        const int rt = tid - 160;                // 0..95
        // stage R rows [nhalf*64, nhalf*64+64) -> local rows 0..63
        const float4* Rg = (const float4*)(relm + (size_t)r * D * D) + (nhalf << 6) * 32;
        for (int idx4 = rt; idx4 < 2048; idx4 += 96) {
            float4 v = Rg[idx4];
            int row = idx4 >> 5;                 // local 0..63
            int e4  = idx4 & 31;
            uint2 hi, lo;
            split4(v, hi, lo);
            int bo = swz(row, e4 * 8);
            *(uint2*)(sm + OFF_RH + bo) = hi;
            *(uint2*)(sm + OFF_RL + bo) = lo;
        }
    }
    __syncthreads();
    const int n = min(s_cnt, CAP);
    if (n == 0) return;

    // warp role: rowgrp = wid>>2 (16 rows), nqr = wid&3 (16 N cols of this half)
    const int rowgrp = wid >> 2;
    const int nqr    = wid & 3;
    const int s0     = rowgrp * 16;
    const int colbase = (nhalf << 6) + nqr * 16; // global N col base for epilogue

    const int a_row  = s0 + (lane & 7) + ((lane >> 3) & 1) * 8;   // 0..31
    const int a_koff = ((lane >> 4) & 1) * 16;
    const uint32_t ah_base = smem_u32(sm + OFF_AH) + a_row * 256;
    const uint32_t al_base = smem_u32(sm + OFF_AL) + a_row * 256;
    const int a_xor  = (a_row & 7) << 4;
    const int b_rowc = ((lane >> 4) & 1) * 8 + (lane & 7);
    const int b_k    = ((lane >> 3) & 1) * 16;
    const uint32_t rh_u = smem_u32(sm + OFF_RH);
    const uint32_t rl_u = smem_u32(sm + OFF_RL);

    // A-stage mapping: one eighth-row (4 float4) per thread; 32 rows x 8
    const int st_s = tid >> 3;                   // 0..31
    const int st_e = tid & 7;

    const int ntiles = (n + 31) >> 5;
    for (int t = 0; t < ntiles; t++) {
        const int tstart = t << 5;
        const int rows   = min(32, n - tstart);

        // ---- stage A tile (32 rows), zero-pad invalid rows ----
        {
            uint2 hi, lo;
            if (st_s < rows) {
                const int i = sidx[tstart + st_s];
                const int trow = tarr[i];
                if (st_e == 0) srow[st_s] = harr[i];
                const float4* src = (const float4*)(ent + (size_t)trow * D) + st_e * 4;
#pragma unroll
                for (int j = 0; j < 4; j++) {
                    float4 v = src[j];
                    split4(v, hi, lo);
                    int bo = swz(st_s, (st_e * 4 + j) * 8);
                    *(uint2*)(sm + OFF_AH + bo) = hi;
                    *(uint2*)(sm + OFF_AL + bo) = lo;
                }
            } else {
                hi.x = hi.y = 0u;
#pragma unroll
                for (int j = 0; j < 4; j++) {
                    int bo = swz(st_s, (st_e * 4 + j) * 8);
                    *(uint2*)(sm + OFF_AH + bo) = hi;
                    *(uint2*)(sm + OFF_AL + bo) = hi;
                }
            }
        }
        __syncthreads();

        if (s0 < rows) {                          // warp-uniform
            const int rq  = lane >> 2;
            const bool v0 = (s0 + rq) < rows;
            const bool v1 = (s0 + rq + 8) < rows;
            const float* hp0 = ent + (size_t)srow[v0 ? s0 + rq : 0] * D;
            const float* hp1 = ent + (size_t)srow[v1 ? s0 + rq + 8 : 0] * D;
            asm volatile("prefetch.global.L2 [%0];" :: "l"(hp0 + colbase + (lane & 1) * 32));
            asm volatile("prefetch.global.L2 [%0];" :: "l"(hp1 + colbase + (lane & 1) * 32));

            // ---- warp GEMM: 16 rows x 16 N x 128 K, 3-split bf16 ----
            float c[2][4];
            c[0][0] = c[0][1] = c[0][2] = c[0][3] = 0.f;
            c[1][0] = c[1][1] = c[1][2] = c[1][3] = 0.f;

#pragma unroll
            for (int ks = 0; ks < 8; ks++) {
                const int kb = ks * 32;
                uint32_t th0, th1, th2, th3, tl0, tl1, tl2, tl3;
                ldsm_x4(th0, th1, th2, th3, ah_base + ((kb + a_koff) ^ a_xor));
                ldsm_x4(tl0, tl1, tl2, tl3, al_base + ((kb + a_koff) ^ a_xor));
                const int nrow = nqr * 16 + b_rowc;          // local R row 0..63
                const uint32_t boff = nrow * 256 + ((kb + b_k) ^ ((nrow & 7) << 4));
                uint32_t bh0, bh1, bh2, bh3, bl0, bl1, bl2, bl3;
                ldsm_x4(bh0, bh1, bh2, bh3, rh_u + boff);
                ldsm_x4(bl0, bl1, bl2, bl3, rl_u + boff);
                mma_bf16(c[0][0], c[0][1], c[0][2], c[0][3],
                         th0, th1, th2, th3, bh0, bh1);
                mma_bf16(c[0][0], c[0][1], c[0][2], c[0][3],
                         th0, th1, th2, th3, bl0, bl1);
                mma_bf16(c[0][0], c[0][1], c[0][2], c[0][3],
                         tl0, tl1, tl2, tl3, bh0, bh1);
                mma_bf16(c[1][0], c[1][1], c[1][2], c[1][3],
                         th0, th1, th2, th3, bh2, bh3);
                mma_bf16(c[1][0], c[1][1], c[1][2], c[1][3],
                         th0, th1, th2, th3, bl2, bl3);
                mma_bf16(c[1][0], c[1][1], c[1][2], c[1][3],
                         tl0, tl1, tl2, tl3, bh2, bh3);
            }

            // ---- partial epilogue: dot with H over this warp's 16 N cols ----
            const int coff = 2 * (lane & 3);
            float acc0 = 0.f, acc1 = 0.f;
#pragma unroll
            for (int nt = 0; nt < 2; nt++) {
                const int col = colbase + nt * 8 + coff;
                float2 h0 = *(const float2*)(hp0 + col);
                float2 h1 = *(const float2*)(hp1 + col);
                acc0 = fmaf(c[nt][0], h0.x, acc0);
                acc0 = fmaf(c[nt][1], h0.y, acc0);
                acc1 = fmaf(c[nt][2], h1.x, acc1);
                acc1 = fmaf(c[nt][3], h1.y, acc1);
            }
#pragma unroll
            for (int o = 1; o < 4; o <<= 1) {
                acc0 += __shfl_xor_sync(0xffffffffu, acc0, o);
                acc1 += __shfl_xor_sync(0xffffffffu, acc1, o);
            }
            if ((lane & 3) == 0) {
                if (v0) psc[(s0 + rq) * 4 + nqr]     = acc0;
                if (v1) psc[(s0 + rq + 8) * 4 + nqr] = acc1;
            }
        }
        __syncthreads();

        // ---- combine quarters; exactly 2 atomicAdds per output (deterministic) ----
        if (tid < rows) {
            float s = psc[tid * 4 + 0] + psc[tid * 4 + 1]
                    + psc[tid * 4 + 2] + psc[tid * 4 + 3];
            atomicAdd(&out[(side ? B : 0) + sidx[tstart + tid]], s);
        }
        __syncthreads();   // psc/A fully consumed before next tile
    }
}

// ---------------- launch ----------------
extern "C" void kernel_launch(void* const* d_in, const int* in_sizes, int n_in,
                              void* d_out, int out_size)
{
    const int*   heads  = (const int*)  d_in[0];
    const int*   tails  = (const int*)  d_in[1];
    const int*   nheads = (const int*)  d_in[2];
    const int*   ntails = (const int*)  d_in[3];
    const int*   rels   = (const int*)  d_in[4];
    const float* ent    = (const float*)d_in[5];
    const float* relm   = (const float*)d_in[6];
    float*       out    = (float*)      d_out;

    const int B    = in_sizes[0];
    const int nrel = in_sizes[6] / (D * D);

    k_zero_out<<<(out_size + 1023) / 1024, 1024>>>(out, out_size);

    cudaFuncSetAttribute(k_rescal, cudaFuncAttributeMaxDynamicSharedMemorySize,
                         SMEM_BYTES);
    k_rescal<<<nrel * 4, NTH, SMEM_BYTES>>>(heads, tails, nheads, ntails, rels,
                                            ent, relm, out, B);
}

// round 17
// speedup vs baseline: 1.2733x; 1.2733x over previous
#include <cuda_runtime.h>
#include <cuda_bf16.h>
#include <cstdint>

#define D    128
#define CAP  1024
#define NTH  512

// smem layout (bytes)
#define OFF_RH   0          // 32KB  (128 rows x 256B, swizzled)
#define OFF_RL   32768      // 32KB
#define OFF_AH   65536      // 16KB  (64 rows x 256B)
#define OFF_AL   81920      // 16KB
#define OFF_SIDX 98304      // 4KB
#define OFF_SROW 102400     // 64*4
#define OFF_PSC  102656     // 64*4*4 = 1KB
#define SMEM_BYTES (102656 + 1024)

// ---------------- helpers ----------------
__device__ __forceinline__ uint32_t smem_u32(const void* p) {
    return (uint32_t)__cvta_generic_to_shared(p);
}
__device__ __forceinline__ int swz(int row, int kbyte) {
    return row * 256 + (kbyte ^ ((row & 7) << 4));
}
__device__ __forceinline__ uint32_t pkbf(__nv_bfloat16 a, __nv_bfloat16 b) {
    return (uint32_t)__bfloat16_as_ushort(a) | ((uint32_t)__bfloat16_as_ushort(b) << 16);
}
__device__ __forceinline__ void split4(float4 v, uint2& hi, uint2& lo) {
    __nv_bfloat16 hx = __float2bfloat16(v.x), hy = __float2bfloat16(v.y);
    __nv_bfloat16 hz = __float2bfloat16(v.z), hw = __float2bfloat16(v.w);
    __nv_bfloat16 lx = __float2bfloat16(v.x - __bfloat162float(hx));
    __nv_bfloat16 ly = __float2bfloat16(v.y - __bfloat162float(hy));
    __nv_bfloat16 lz = __float2bfloat16(v.z - __bfloat162float(hz));
    __nv_bfloat16 lw = __float2bfloat16(v.w - __bfloat162float(hw));
    hi.x = pkbf(hx, hy); hi.y = pkbf(hz, hw);
    lo.x = pkbf(lx, ly); lo.y = pkbf(lz, lw);
}
__device__ __forceinline__ void ldsm_x4(uint32_t& r0, uint32_t& r1,
                                        uint32_t& r2, uint32_t& r3, uint32_t a) {
    asm volatile("ldmatrix.sync.aligned.m8n8.x4.shared.b16 {%0,%1,%2,%3}, [%4];"
                 : "=r"(r0), "=r"(r1), "=r"(r2), "=r"(r3) : "r"(a));
}
__device__ __forceinline__ void mma_bf16(float& c0, float& c1, float& c2, float& c3,
                                         uint32_t a0, uint32_t a1, uint32_t a2,
                                         uint32_t a3, uint32_t b0, uint32_t b1) {
    asm volatile(
        "mma.sync.aligned.m16n8k16.row.col.f32.bf16.bf16.f32 "
        "{%0,%1,%2,%3}, {%4,%5,%6,%7}, {%8,%9}, {%0,%1,%2,%3};"
        : "+f"(c0), "+f"(c1), "+f"(c2), "+f"(c3)
        : "r"(a0), "r"(a1), "r"(a2), "r"(a3), "r"(b0), "r"(b1));
}

// ---------------- main kernel: one CTA per (relation, side) ----------------
extern "C" __global__ void __launch_bounds__(NTH, 2)
k_rescal(const int*   __restrict__ heads,
         const int*   __restrict__ tails,
         const int*   __restrict__ nheads,
         const int*   __restrict__ ntails,
         const int*   __restrict__ rels,
         const float* __restrict__ ent,
         const float* __restrict__ relm,
         float*       __restrict__ out,
         int B)
{
    extern __shared__ char sm[];
    __shared__ int s_cnt;
    int*   sidx = (int*)(sm + OFF_SIDX);
    int*   srow = (int*)(sm + OFF_SROW);     // head-row ids of current tile
    float* psc  = (float*)(sm + OFF_PSC);    // [64 rows][4 quarters]

    const int tid  = threadIdx.x;
    const int wid  = tid >> 5;
    const int lane = tid & 31;
    const int r    = blockIdx.x >> 1;
    const int side = blockIdx.x & 1;
    const int* tarr = side ? ntails : tails;
    const int* harr = side ? nheads : heads;

    if (tid == 0) s_cnt = 0;
    __syncthreads();

    // ---- PHASE 1 (parallel): warps 0-7 filter, warps 8-15 stage R ----
    if (tid < 256) {
        const int4* r4 = (const int4*)rels;
        const int nq = B >> 2;
        auto proc = [&](int4 v, int base) {
            if (v.x == r) { int p = atomicAdd(&s_cnt, 1); if (p < CAP) sidx[p] = base; }
            if (v.y == r) { int p = atomicAdd(&s_cnt, 1); if (p < CAP) sidx[p] = base + 1; }
            if (v.z == r) { int p = atomicAdd(&s_cnt, 1); if (p < CAP) sidx[p] = base + 2; }
            if (v.w == r) { int p = atomicAdd(&s_cnt, 1); if (p < CAP) sidx[p] = base + 3; }
        };
        if ((nq & 2047) == 0) {
            // batched: issue 8 independent int4 loads, then process
            for (int base = 0; base < nq; base += 2048) {
                int q = base + tid;
                int4 v0 = r4[q];
                int4 v1 = r4[q + 256];
                int4 v2 = r4[q + 512];
                int4 v3 = r4[q + 768];
                int4 v4 = r4[q + 1024];
                int4 v5 = r4[q + 1280];
                int4 v6 = r4[q + 1536];
                int4 v7 = r4[q + 1792];
                proc(v0, q << 2);
                proc(v1, (q + 256) << 2);
                proc(v2, (q + 512) << 2);
                proc(v3, (q + 768) << 2);
                proc(v4, (q + 1024) << 2);
                proc(v5, (q + 1280) << 2);
                proc(v6, (q + 1536) << 2);
                proc(v7, (q + 1792) << 2);
            }
        } else {
            for (int q = tid; q < nq; q += 256) proc(r4[q], q << 2);
            for (int i = (nq << 2) + tid; i < B; i += 256)
                if (rels[i] == r) { int p = atomicAdd(&s_cnt, 1); if (p < CAP) sidx[p] = i; }
        }
    } else {
        const int rt = tid - 256;
        const float4* Rg = (const float4*)(relm + (size_t)r * D * D);
#pragma unroll
        for (int k = 0; k < 16; k++) {
            int idx4 = rt + k * 256;             // 0..4095
            float4 v = Rg[idx4];
            int row = idx4 >> 5;
            int e4  = idx4 & 31;
            uint2 hi, lo;
            split4(v, hi, lo);
            int bo = swz(row, e4 * 8);
            *(uint2*)(sm + OFF_RH + bo) = hi;
            *(uint2*)(sm + OFF_RL + bo) = lo;
        }
    }
    __syncthreads();
    const int n = min(s_cnt, CAP);
    if (n == 0) return;

    // warp role: rowgrp = wid>>2 (16 rows), nqr = wid&3 (32 N cols)
    const int rowgrp = wid >> 2;
    const int nqr    = wid & 3;
    const int s0     = rowgrp * 16;

    const int a_row  = s0 + (lane & 7) + ((lane >> 3) & 1) * 8;
    const int a_koff = ((lane >> 4) & 1) * 16;
    const uint32_t ah_base = smem_u32(sm + OFF_AH) + a_row * 256;
    const uint32_t al_base = smem_u32(sm + OFF_AL) + a_row * 256;
    const int a_xor  = (a_row & 7) << 4;
    const int b_rowc = ((lane >> 4) & 1) * 8 + (lane & 7);
    const int b_k    = ((lane >> 3) & 1) * 16;
    const uint32_t rh_u = smem_u32(sm + OFF_RH);
    const uint32_t rl_u = smem_u32(sm + OFF_RL);

    // A-stage mapping: one eighth-row (4 float4) per thread; 64 rows x 8
    const int st_s = tid >> 3;
    const int st_e = tid & 7;

    const int ntiles = (n + 63) >> 6;
    for (int t = 0; t < ntiles; t++) {
        const int tstart = t << 6;
        const int rows   = min(64, n - tstart);

        // ---- stage A tile (64 rows), zero-pad invalid rows ----
        {
            uint2 hi, lo;
            if (st_s < rows) {
                const int i = sidx[tstart + st_s];
                const int trow = tarr[i];
                if (st_e == 0) srow[st_s] = harr[i];
                const float4* src = (const float4*)(ent + (size_t)trow * D) + st_e * 4;
#pragma unroll
                for (int j = 0; j < 4; j++) {
                    float4 v = src[j];
                    split4(v, hi, lo);
                    int bo = swz(st_s, (st_e * 4 + j) * 8);
                    *(uint2*)(sm + OFF_AH + bo) = hi;
                    *(uint2*)(sm + OFF_AL + bo) = lo;
                }
            } else {
                hi.x = hi.y = 0u;
#pragma unroll
                for (int j = 0; j < 4; j++) {
                    int bo = swz(st_s, (st_e * 4 + j) * 8);
                    *(uint2*)(sm + OFF_AH + bo) = hi;
                    *(uint2*)(sm + OFF_AL + bo) = hi;
                }
            }
        }
        __syncthreads();

        if (s0 < rows) {                          // warp-uniform
            // ---- prefetch H rows into L2 (overlaps with MMA) ----
            const int rq  = lane >> 2;
            const bool v0 = (s0 + rq) < rows;
            const bool v1 = (s0 + rq + 8) < rows;
            const float* hp0 = ent + (size_t)srow[v0 ? s0 + rq : 0] * D;
            const float* hp1 = ent + (size_t)srow[v1 ? s0 + rq + 8 : 0] * D;
            asm volatile("prefetch.global.L2 [%0];" :: "l"(hp0 + (lane & 3) * 32));
            asm volatile("prefetch.global.L2 [%0];" :: "l"(hp1 + (lane & 3) * 32));

            // ---- warp GEMM: 16 rows x 32 N x 128 K, 3-split bf16 ----
            float c[4][4];
#pragma unroll
            for (int nt = 0; nt < 4; nt++)
                c[nt][0] = c[nt][1] = c[nt][2] = c[nt][3] = 0.f;

#pragma unroll
            for (int ks = 0; ks < 8; ks++) {
                const int kb = ks * 32;
                uint32_t th0, th1, th2, th3, tl0, tl1, tl2, tl3;
                ldsm_x4(th0, th1, th2, th3, ah_base + ((kb + a_koff) ^ a_xor));
                ldsm_x4(tl0, tl1, tl2, tl3, al_base + ((kb + a_koff) ^ a_xor));
#pragma unroll
                for (int ntp = 0; ntp < 2; ntp++) {
                    const int nrow = nqr * 32 + ntp * 16 + b_rowc;
                    const uint32_t boff = nrow * 256 + ((kb + b_k) ^ ((nrow & 7) << 4));
                    uint32_t bh0, bh1, bh2, bh3, bl0, bl1, bl2, bl3;
                    ldsm_x4(bh0, bh1, bh2, bh3, rh_u + boff);
                    ldsm_x4(bl0, bl1, bl2, bl3, rl_u + boff);
                    const int nt = ntp * 2;
                    mma_bf16(c[nt][0], c[nt][1], c[nt][2], c[nt][3],
                             th0, th1, th2, th3, bh0, bh1);
                    mma_bf16(c[nt][0], c[nt][1], c[nt][2], c[nt][3],
                             th0, th1, th2, th3, bl0, bl1);
                    mma_bf16(c[nt][0], c[nt][1], c[nt][2], c[nt][3],
                             tl0, tl1, tl2, tl3, bh0, bh1);
                    mma_bf16(c[nt + 1][0], c[nt + 1][1], c[nt + 1][2], c[nt + 1][3],
                             th0, th1, th2, th3, bh2, bh3);
                    mma_bf16(c[nt + 1][0], c[nt + 1][1], c[nt + 1][2], c[nt + 1][3],
                             th0, th1, th2, th3, bl2, bl3);
                    mma_bf16(c[nt + 1][0], c[nt + 1][1], c[nt + 1][2], c[nt + 1][3],
                             tl0, tl1, tl2, tl3, bh2, bh3);
                }
            }

            // ---- partial epilogue: dot with H over this warp's 32 N cols ----
            const int coff = 2 * (lane & 3);
            float acc0 = 0.f, acc1 = 0.f;
#pragma unroll
            for (int nt = 0; nt < 4; nt++) {
                const int col = nqr * 32 + nt * 8 + coff;
                float2 h0 = *(const float2*)(hp0 + col);
                float2 h1 = *(const float2*)(hp1 + col);
                acc0 = fmaf(c[nt][0], h0.x, acc0);
                acc0 = fmaf(c[nt][1], h0.y, acc0);
                acc1 = fmaf(c[nt][2], h1.x, acc1);
                acc1 = fmaf(c[nt][3], h1.y, acc1);
            }
#pragma unroll
            for (int o = 1; o < 4; o <<= 1) {
                acc0 += __shfl_xor_sync(0xffffffffu, acc0, o);
                acc1 += __shfl_xor_sync(0xffffffffu, acc1, o);
            }
            if ((lane & 3) == 0) {
                if (v0) psc[(s0 + rq) * 4 + nqr]     = acc0;
                if (v1) psc[(s0 + rq + 8) * 4 + nqr] = acc1;
            }
        }
        __syncthreads();

        // ---- combine quarters, write out ----
        if (tid < rows) {
            float s = psc[tid * 4 + 0] + psc[tid * 4 + 1]
                    + psc[tid * 4 + 2] + psc[tid * 4 + 3];
            out[(side ? B : 0) + sidx[tstart + tid]] = s;
        }
        __syncthreads();   // psc/A fully consumed before next tile
    }
}

// ---------------- launch ----------------
extern "C" void kernel_launch(void* const* d_in, const int* in_sizes, int n_in,
                              void* d_out, int out_size)
{
    const int*   heads  = (const int*)  d_in[0];
    const int*   tails  = (const int*)  d_in[1];
    const int*   nheads = (const int*)  d_in[2];
    const int*   ntails = (const int*)  d_in[3];
    const int*   rels   = (const int*)  d_in[4];
    const float* ent    = (const float*)d_in[5];
    const float* relm   = (const float*)d_in[6];
    float*       out    = (float*)      d_out;

    const int B    = in_sizes[0];
    const int nrel = in_sizes[6] / (D * D);

    cudaFuncSetAttribute(k_rescal, cudaFuncAttributeMaxDynamicSharedMemorySize,
                         SMEM_BYTES);
    k_rescal<<<nrel * 2, NTH, SMEM_BYTES>>>(heads, tails, nheads, ntails, rels,
                                            ent, relm, out, B);
}